// round 16
// baseline (speedup 1.0000x reference)
#include <cuda_runtime.h>
#include <cuda_bf16.h>
#include <cstdint>

#define N_ETA 7
#define FDIM 68
#define HW (512*1024)
#define CCH 2048
#define NCHK (HW / CCH)           // 256
#define SLOTSC 2816               // 22 tiles * 128
#define MAXT 22
#define KP 72                     // bf16 feature words per px (68 + 4 zero), 144 B

#define AS 88                     // smem row stride in bf16 elems (176 B)
#define APLANE (80*AS*2)          // 14080 B per W plane
#define BPLANE (128*AS*2)         // 22528 B per B plane
#define AH_OFF 0
#define AL_OFF APLANE
#define BH_OFF (2*APLANE)
#define BL_OFF (2*APLANE + BPLANE)
#define SL_OFF (2*APLANE + 2*BPLANE)          // 73216
#define SMEMC (SL_OFF + 256)                  // 73472 B

__device__ __align__(16) __nv_bfloat16 g_fhi[(size_t)HW * KP];
__device__ __align__(16) __nv_bfloat16 g_flo[(size_t)HW * KP];
__device__ __align__(16) char g_wimg[14 * APLANE];   // [hi e0..e6, lo e0..e6], [80][88] bf16 zero-padded
__device__ uint16_t g_slots[NCHK * SLOTSC];          // bits[0:11) local px, [11] valid
__device__ int g_te[NCHK * MAXT];
__device__ int g_nt[NCHK];

__device__ __forceinline__ void threefry2x32_k42(uint32_t& x0, uint32_t& x1) {
    const uint32_t K2 = 0x1BD11BDAu ^ 0u ^ 42u;
#define TFR(r) { x0 += x1; x1 = __funnelshift_l(x1, x1, (r)); x1 ^= x0; }
    x1 += 42u;
    TFR(13) TFR(15) TFR(26) TFR(6)
    x0 += 42u;  x1 += K2 + 1u;
    TFR(17) TFR(29) TFR(16) TFR(24)
    x0 += K2;   x1 += 0u + 2u;
    TFR(13) TFR(15) TFR(26) TFR(6)
    x1 += 42u + 3u;
    TFR(17) TFR(29) TFR(16) TFR(24)
    x0 += 42u;  x1 += K2 + 4u;
    TFR(13) TFR(15) TFR(26) TFR(6)
    x0 += K2;   x1 += 0u + 5u;
#undef TFR
}
__device__ __forceinline__ float gumbel_from_bits(uint32_t bits) {
    float f = __uint_as_float((bits >> 9) | 0x3F800000u) - 1.0f;
    const float tiny = 1.1754943508222875e-38f;
    float u = fmaxf(tiny, f + tiny);
    return -logf(-logf(u));
}

__global__ __launch_bounds__(1024)
void eta_sort_kernel(const float* __restrict__ T, const int* __restrict__ eta) {
    __shared__ float logT[49];
    __shared__ uint16_t ent[SLOTSC];
    __shared__ int hist[N_ETA], start[N_ETA + 1], cur[N_ETA];
    const int tid = threadIdx.x, c = blockIdx.x, cb = c * CCH;
    if (tid < 49) logT[tid] = logf(T[tid] + 1e-9f);
    if (tid < N_ETA) hist[tid] = 0;
    for (int s = tid; s < SLOTSC; s += 1024) ent[s] = 0;
    __syncthreads();
    int myE[2];
#pragma unroll
    for (int r = 0; r < 2; r++) {
        int lp = tid + r * 1024, p = cb + lp, rr = eta[p] * N_ETA;
        float best = -3.0e38f; int a = 0;
#pragma unroll
        for (int k = 0; k < N_ETA; k++) {
            uint32_t x0 = 0u, x1 = (uint32_t)(p * 7 + k);
            threefry2x32_k42(x0, x1);
            float v = logT[rr + k] + gumbel_from_bits(x0 ^ x1);
            if (v > best) { best = v; a = k; }
        }
        myE[r] = a;
        atomicAdd(&hist[a], 1);
    }
    __syncthreads();
    if (tid == 0) {
        int s = 0, tt = 0;
        for (int e = 0; e < N_ETA; e++) {
            start[e] = s; cur[e] = s;
            int pe = (hist[e] + 127) & ~127;
            for (int q = 0; q < (pe >> 7); q++) g_te[c * MAXT + tt++] = e;
            s += pe;
        }
        start[N_ETA] = s;
        g_nt[c] = s >> 7;
    }
    __syncthreads();
#pragma unroll
    for (int r = 0; r < 2; r++) {
        int pos = atomicAdd(&cur[myE[r]], 1);
        ent[pos] = (uint16_t)((tid + r * 1024) | (1 << 11));
    }
    __syncthreads();
    const int tot = start[N_ETA];
    for (int s = tid; s < tot; s += 1024) {
        if (ent[s] == 0) {
            int e = 0;
#pragma unroll
            for (int k = 1; k < N_ETA; k++) if (s >= start[k]) e = k;
            ent[s] = (uint16_t)(ent[start[e]] & 0x7FF);   // pad: dup first real px, valid=0
        }
    }
    __syncthreads();
    for (int s = tid; s < tot; s += 1024) g_slots[c * SLOTSC + s] = ent[s];
}

__device__ __forceinline__ void split_bf(float v, unsigned short& hi, unsigned short& lo) {
    __nv_bfloat16 h = __float2bfloat16(v);
    __nv_bfloat16 l = __float2bfloat16(v - __bfloat162float(h));
    hi = ((__nv_bfloat16_raw&)h).x; lo = ((__nv_bfloat16_raw&)l).x;
}

__global__ __launch_bounds__(256)
void prep_feat_kernel(const float* __restrict__ feat) {
    const int px = blockIdx.x * 256 + threadIdx.x;
    uint32_t ph[36], pl[36];
#pragma unroll
    for (int fp = 0; fp < 34; fp++) {
        unsigned short h0, l0, h1, l1;
        split_bf(feat[(size_t)(2 * fp) * HW + px], h0, l0);
        split_bf(feat[(size_t)(2 * fp + 1) * HW + px], h1, l1);
        ph[fp] = (uint32_t)h0 | ((uint32_t)h1 << 16);
        pl[fp] = (uint32_t)l0 | ((uint32_t)l1 << 16);
    }
    ph[34] = ph[35] = pl[34] = pl[35] = 0;
    uint4* dh = (uint4*)(g_fhi + (size_t)px * KP);
    uint4* dl = (uint4*)(g_flo + (size_t)px * KP);
#pragma unroll
    for (int q = 0; q < 9; q++) {
        dh[q] = make_uint4(ph[4*q], ph[4*q+1], ph[4*q+2], ph[4*q+3]);
        dl[q] = make_uint4(pl[4*q], pl[4*q+1], pl[4*q+2], pl[4*q+3]);
    }
}

__global__ __launch_bounds__(512)
void prep_w_kernel(const float* __restrict__ W) {
    const int tid = threadIdx.x;
    for (int i = tid; i < 14 * APLANE / 4; i += 512) ((uint32_t*)g_wimg)[i] = 0;
    __syncthreads();
    for (int i = tid; i < N_ETA * FDIM * FDIM; i += 512) {
        int e = i / (FDIM * FDIM), rem = i - e * (FDIM * FDIM);
        int o = rem / FDIM, f = rem - o * FDIM;
        unsigned short hi, lo;
        split_bf(W[i], hi, lo);
        *(unsigned short*)(g_wimg + e * APLANE + o * (AS * 2) + f * 2) = hi;
        *(unsigned short*)(g_wimg + (7 + e) * APLANE + o * (AS * 2) + f * 2) = lo;
    }
}

__device__ __forceinline__ uint32_t s2u(const void* p) { return (uint32_t)__cvta_generic_to_shared(p); }
__device__ __forceinline__ void cp16(void* dst, const void* src) {
    asm volatile("cp.async.ca.shared.global [%0], [%1], 16;" :: "r"(s2u(dst)), "l"(src));
}
#define CP_COMMIT() asm volatile("cp.async.commit_group;" ::: "memory")
#define CP_WAIT0()  asm volatile("cp.async.wait_group 0;" ::: "memory")

// mma.sync m16n8k16 row.col f32.bf16.bf16.f32 — baseline PTX (sm_80+), compiles for compute_103
__device__ __forceinline__ void mma16816(float* c, const uint32_t* a, uint32_t b0, uint32_t b1) {
    asm volatile(
        "mma.sync.aligned.m16n8k16.row.col.f32.bf16.bf16.f32 "
        "{%0,%1,%2,%3}, {%4,%5,%6,%7}, {%8,%9}, {%0,%1,%2,%3};"
        : "+f"(c[0]), "+f"(c[1]), "+f"(c[2]), "+f"(c[3])
        : "r"(a[0]), "r"(a[1]), "r"(a[2]), "r"(a[3]), "r"(b0), "r"(b1));
}

// One block per 2048-px chunk. Per expert-pure 128-px tile:
//   A(W) [80][88] bf16 hi/lo smem (copied on expert change, zero-padded image)
//   B(feat) [128 n][88 k] bf16 hi/lo, gathered from px-major planes via cp.async
//   4 warps x 4 n-tiles x 5 m-tiles x 5 k-steps x 3 split-products of m16n8k16.
__global__ __launch_bounds__(128, 1)
void compute_kernel(const float* __restrict__ bias, float* __restrict__ out) {
    extern __shared__ char smc[];
    uint16_t* smsl = (uint16_t*)(smc + SL_OFF);
    const int tid = threadIdx.x, wid = tid >> 5, lane = tid & 31;
    const int qr = lane >> 2, qc = lane & 3;
    const int n0 = wid * 32;

    for (int i = tid; i < SMEMC / 4; i += 128) ((uint32_t*)smc)[i] = 0;   // pads stay 0 forever
    __syncthreads();

    const int c = blockIdx.x;
    const int cb = c * CCH;
    const int nt = g_nt[c];
    int pe = -1;

    for (int t = 0; t < nt; t++) {
        const int e = g_te[c * MAXT + t];
        if (e != pe) {
            pe = e;
            const char* sH = g_wimg + e * APLANE;
            const char* sL = g_wimg + (7 + e) * APLANE;
            for (int i = tid; i < APLANE / 16; i += 128) {
                cp16(smc + AH_OFF + i * 16, sH + i * 16);
                cp16(smc + AL_OFF + i * 16, sL + i * 16);
            }
        }
        const uint16_t* sl = g_slots + c * SLOTSC + t * 128;
        smsl[tid] = sl[tid];
        for (int i = tid; i < 2304; i += 128) {       // 128 n * 9 units * 2 planes
            int pl = (i >= 1152);
            int j = i - pl * 1152;
            int n = j / 9, u = j - n * 9;
            int px = cb + (sl[n] & 0x7FF);
            cp16(smc + (pl ? BL_OFF : BH_OFF) + n * (AS * 2) + u * 16,
                 (pl ? g_flo : g_fhi) + (size_t)px * KP + u * 8);
        }
        CP_COMMIT();
        CP_WAIT0();
        __syncthreads();

        float acc[5][4][4];
#pragma unroll
        for (int m = 0; m < 5; m++)
#pragma unroll
            for (int j = 0; j < 4; j++)
#pragma unroll
                for (int q = 0; q < 4; q++) acc[m][j][q] = 0.f;

#pragma unroll
        for (int ks = 0; ks < 5; ks++) {
            const int k0 = ks * 16;
            uint32_t ah[5][4], al[5][4];
#pragma unroll
            for (int m = 0; m < 5; m++) {
                const char* bp = smc + (m * 16 + qr) * (AS * 2) + (k0 + 2 * qc) * 2;
                ah[m][0] = *(const uint32_t*)(bp + AH_OFF);
                ah[m][1] = *(const uint32_t*)(bp + AH_OFF + 8 * AS * 2);
                ah[m][2] = *(const uint32_t*)(bp + AH_OFF + 16);
                ah[m][3] = *(const uint32_t*)(bp + AH_OFF + 8 * AS * 2 + 16);
                al[m][0] = *(const uint32_t*)(bp + AL_OFF);
                al[m][1] = *(const uint32_t*)(bp + AL_OFF + 8 * AS * 2);
                al[m][2] = *(const uint32_t*)(bp + AL_OFF + 16);
                al[m][3] = *(const uint32_t*)(bp + AL_OFF + 8 * AS * 2 + 16);
            }
#pragma unroll
            for (int j = 0; j < 4; j++) {
                const char* vp = smc + (n0 + j * 8 + qr) * (AS * 2) + (k0 + 2 * qc) * 2;
                uint32_t bh0 = *(const uint32_t*)(vp + BH_OFF);
                uint32_t bh1 = *(const uint32_t*)(vp + BH_OFF + 16);
                uint32_t bl0 = *(const uint32_t*)(vp + BL_OFF);
                uint32_t bl1 = *(const uint32_t*)(vp + BL_OFF + 16);
#pragma unroll
                for (int m = 0; m < 5; m++) {
                    mma16816(acc[m][j], ah[m], bh0, bh1);
                    mma16816(acc[m][j], ah[m], bl0, bl1);
                    mma16816(acc[m][j], al[m], bh0, bh1);
                }
            }
        }

        // epilogue: C frag rows r = 16m+qr (+8), cols n = n0+8j+2qc (+1); masked scatter
#pragma unroll
        for (int m = 0; m < 5; m++) {
            const int r0 = m * 16 + qr, r1 = r0 + 8;
            const float bv0 = (r0 < FDIM) ? __ldg(bias + e * FDIM + r0) : 0.f;
            const float bv1 = (r1 < FDIM) ? __ldg(bias + e * FDIM + r1) : 0.f;
#pragma unroll
            for (int j = 0; j < 4; j++) {
                const int nA = n0 + j * 8 + qc * 2, nB = nA + 1;
                const uint16_t eA = smsl[nA], eB = smsl[nB];
                if (r0 < FDIM) {
                    float* row = out + (size_t)r0 * HW + cb;
                    if (eA & 0x800) row[eA & 0x7FF] = acc[m][j][0] + bv0;
                    if (eB & 0x800) row[eB & 0x7FF] = acc[m][j][1] + bv0;
                }
                if (r1 < FDIM) {
                    float* row = out + (size_t)r1 * HW + cb;
                    if (eA & 0x800) row[eA & 0x7FF] = acc[m][j][2] + bv1;
                    if (eB & 0x800) row[eB & 0x7FF] = acc[m][j][3] + bv1;
                }
            }
        }
        __syncthreads();   // smem safe to restage
    }
}

extern "C" void kernel_launch(void* const* d_in, const int* in_sizes, int n_in,
                              void* d_out, int out_size) {
    const float* x = 0; const float* W = 0; const float* b = 0;
    const float* T = 0; const int* eta = 0;
    for (int i = 0; i < n_in; i++) {
        switch (in_sizes[i]) {
            case 35651584: x   = (const float*)d_in[i]; break;
            case 32368:    W   = (const float*)d_in[i]; break;
            case 476:      b   = (const float*)d_in[i]; break;
            case 49:       T   = (const float*)d_in[i]; break;
            case 524288:   eta = (const int*)d_in[i];   break;
        }
    }
    float* out = (float*)d_out;

    eta_sort_kernel<<<NCHK, 1024>>>(T, eta);
    prep_feat_kernel<<<HW / 256, 256>>>(x);
    prep_w_kernel<<<1, 512>>>(W);

    cudaFuncSetAttribute(compute_kernel, cudaFuncAttributeMaxDynamicSharedMemorySize, SMEMC);
    compute_kernel<<<NCHK, 128, SMEMC>>>(b, out);
}